// round 1
// baseline (speedup 1.0000x reference)
#include <cuda_runtime.h>
#include <cuda_bf16.h>
#include <cstdint>

#define HID   4096
#define NH    32
#define HD    128
#define BATCH 2
#define SEQ   2048
#define MTOK  (BATCH*SEQ)   /* 4096 tokens */
#define BH    (BATCH*NH)    /* 64 (batch, head) pairs */

typedef unsigned long long ull;

// Scratch: Q|K|V each [bh][s][d] fp32 (64 MB each), plus softmax stats.
__device__ float g_qkv[3ULL * MTOK * HID];
__device__ float g_m[BH * SEQ];
__device__ float g_l[BH * SEQ];

// ---------------- packed f32x2 helpers ----------------
__device__ __forceinline__ void fma2(ull &d, ull a, ull b) {
    asm("fma.rn.f32x2 %0, %1, %2, %0;" : "+l"(d) : "l"(a), "l"(b));
}
__device__ __forceinline__ ull packdup(float x) {
    unsigned u = __float_as_uint(x);
    return ((ull)u << 32) | (ull)u;
}
__device__ __forceinline__ float lo32(ull v) { return __uint_as_float((unsigned)v); }
__device__ __forceinline__ float hi32(ull v) { return __uint_as_float((unsigned)(v >> 32)); }

// =======================================================================
// Kernel 1: Y[m,n] = sum_k X[m,k] * W[n,k]   (torch Linear, y = x @ W^T)
// Writes result into scratch laid out as [b*NH+h][s][d].
// Block tile 128x128, K-step 16, 256 threads, 8x8 micro-tile (split cols).
// =======================================================================
__global__ __launch_bounds__(256, 1)
void gemm_qkv(const float* __restrict__ X, const float* __restrict__ W,
              float* __restrict__ dst) {
    __shared__ ull   As2[16][128];   // A duplicated-pair (broadcast operand)
    __shared__ float Bs[16][128];

    const int t  = threadIdx.x;
    const int bm = blockIdx.y * 128;
    const int bn = blockIdx.x * 128;
    const int lrow  = t & 127;
    const int lhalf = t >> 7;        // which k-quartet
    const float* Ag = X + (size_t)(bm + lrow) * HID;
    const float* Bg = W + (size_t)(bn + lrow) * HID;

    const int ty = t >> 4, tx = t & 15;
    const int tm = ty * 8, c0 = tx * 4;

    ull acc[8][4];
#pragma unroll
    for (int i = 0; i < 8; i++)
#pragma unroll
        for (int j = 0; j < 4; j++) acc[i][j] = 0ULL;

    for (int k0 = 0; k0 < HID; k0 += 16) {
        float4 a0 = *(const float4*)(Ag + k0 + lhalf * 4);
        float4 a1 = *(const float4*)(Ag + k0 + 8 + lhalf * 4);
        float4 b0 = *(const float4*)(Bg + k0 + lhalf * 4);
        float4 b1 = *(const float4*)(Bg + k0 + 8 + lhalf * 4);
        __syncthreads();
        {
            int kq = lhalf * 4;
            As2[kq + 0][lrow] = packdup(a0.x);
            As2[kq + 1][lrow] = packdup(a0.y);
            As2[kq + 2][lrow] = packdup(a0.z);
            As2[kq + 3][lrow] = packdup(a0.w);
            As2[8 + kq + 0][lrow] = packdup(a1.x);
            As2[8 + kq + 1][lrow] = packdup(a1.y);
            As2[8 + kq + 2][lrow] = packdup(a1.z);
            As2[8 + kq + 3][lrow] = packdup(a1.w);
            Bs[kq + 0][lrow] = b0.x;  Bs[kq + 1][lrow] = b0.y;
            Bs[kq + 2][lrow] = b0.z;  Bs[kq + 3][lrow] = b0.w;
            Bs[8 + kq + 0][lrow] = b1.x;  Bs[8 + kq + 1][lrow] = b1.y;
            Bs[8 + kq + 2][lrow] = b1.z;  Bs[8 + kq + 3][lrow] = b1.w;
        }
        __syncthreads();
#pragma unroll
        for (int kk = 0; kk < 16; kk++) {
            ull a2[8];
#pragma unroll
            for (int i = 0; i < 8; i++) a2[i] = As2[kk][tm + i];
            ulonglong2 bA = *(const ulonglong2*)&Bs[kk][c0];
            ulonglong2 bB = *(const ulonglong2*)&Bs[kk][64 + c0];
#pragma unroll
            for (int i = 0; i < 8; i++) {
                fma2(acc[i][0], a2[i], bA.x);
                fma2(acc[i][1], a2[i], bA.y);
                fma2(acc[i][2], a2[i], bB.x);
                fma2(acc[i][3], a2[i], bB.y);
            }
        }
    }

    // Epilogue: n-tile is 128-wide and 128-aligned -> whole tile is one head.
    const int h = bn >> 7;
#pragma unroll
    for (int i = 0; i < 8; i++) {
        int m = bm + tm + i;
        int b = m >> 11, s = m & 2047;
        float* drow = dst + ((size_t)(b * NH + h) * SEQ + s) * HD;
        float4 o0 = make_float4(lo32(acc[i][0]), hi32(acc[i][0]),
                                lo32(acc[i][1]), hi32(acc[i][1]));
        float4 o1 = make_float4(lo32(acc[i][2]), hi32(acc[i][2]),
                                lo32(acc[i][3]), hi32(acc[i][3]));
        *(float4*)(drow + c0)      = o0;
        *(float4*)(drow + 64 + c0) = o1;
    }
}

// =======================================================================
// Pass 1: per (bh, q-tile of 128): compute scaled S = (Q/sqrt(d)) K^T,
// write raw S to attn buffer, keep online row max / sum(exp).
// smem: Qs2 (packed-dup, [d][m]) 128KB + Ks ([d][n]) 64KB = 192KB dynamic.
// =======================================================================
__global__ __launch_bounds__(256, 1)
void attn_pass1(const float* __restrict__ q_s, const float* __restrict__ k_s,
                float* __restrict__ attn) {
    extern __shared__ char smem[];
    ull   (*Qs2)[128] = reinterpret_cast<ull(*)[128]>(smem);
    float (*Ks)[128]  = reinterpret_cast<float(*)[128]>(smem + 131072);

    const int t  = threadIdx.x;
    const int bh = blockIdx.y;
    const int q0 = blockIdx.x * 128;
    const float scale = 0.08838834764831845f;  // 1/sqrt(128)

    const float* Qg = q_s + ((size_t)bh * SEQ + q0) * HD;
    const float* Kg = k_s + (size_t)bh * SEQ * HD;
    float* attnB = attn + (size_t)bh * SEQ * SEQ;

    const int lrow = t & 127, lhalf = t >> 7;
    // Load Q tile transposed + scaled + pair-duplicated (once per block).
    {
        const float4* src = (const float4*)(Qg + (size_t)lrow * HD);
#pragma unroll 4
        for (int i = 0; i < 16; i++) {
            int d4 = i * 2 + lhalf;
            float4 v = src[d4];
            Qs2[4 * d4 + 0][lrow] = packdup(v.x * scale);
            Qs2[4 * d4 + 1][lrow] = packdup(v.y * scale);
            Qs2[4 * d4 + 2][lrow] = packdup(v.z * scale);
            Qs2[4 * d4 + 3][lrow] = packdup(v.w * scale);
        }
    }
    const int ty = t >> 4, tx = t & 15;
    const int tm = ty * 8, c0 = tx * 4;

    float mrun[8], lrun[8];
#pragma unroll
    for (int i = 0; i < 8; i++) { mrun[i] = -1e30f; lrun[i] = 0.0f; }

    for (int kt = 0; kt < 16; kt++) {
        __syncthreads();  // prior compute done before overwriting Ks (also orders Qs2 on kt=0)
        {
            const float4* ksrc = (const float4*)(Kg + (size_t)(kt * 128 + lrow) * HD);
#pragma unroll 4
            for (int i = 0; i < 16; i++) {
                int d4 = i * 2 + lhalf;
                float4 v = ksrc[d4];
                Ks[4 * d4 + 0][lrow] = v.x;
                Ks[4 * d4 + 1][lrow] = v.y;
                Ks[4 * d4 + 2][lrow] = v.z;
                Ks[4 * d4 + 3][lrow] = v.w;
            }
        }
        __syncthreads();

        ull acc[8][4];
#pragma unroll
        for (int i = 0; i < 8; i++)
#pragma unroll
            for (int j = 0; j < 4; j++) acc[i][j] = 0ULL;

#pragma unroll 8
        for (int kk = 0; kk < 128; kk++) {
            ull a2[8];
#pragma unroll
            for (int i = 0; i < 8; i++) a2[i] = Qs2[kk][tm + i];
            ulonglong2 bA = *(const ulonglong2*)&Ks[kk][c0];
            ulonglong2 bB = *(const ulonglong2*)&Ks[kk][64 + c0];
#pragma unroll
            for (int i = 0; i < 8; i++) {
                fma2(acc[i][0], a2[i], bA.x);
                fma2(acc[i][1], a2[i], bA.y);
                fma2(acc[i][2], a2[i], bB.x);
                fma2(acc[i][3], a2[i], bB.y);
            }
        }

        // Online stats + write raw scaled scores.
#pragma unroll
        for (int i = 0; i < 8; i++) {
            float f0 = lo32(acc[i][0]), f1 = hi32(acc[i][0]);
            float f2 = lo32(acc[i][1]), f3 = hi32(acc[i][1]);
            float f4 = lo32(acc[i][2]), f5 = hi32(acc[i][2]);
            float f6 = lo32(acc[i][3]), f7 = hi32(acc[i][3]);
            float tmax = fmaxf(fmaxf(fmaxf(f0, f1), fmaxf(f2, f3)),
                               fmaxf(fmaxf(f4, f5), fmaxf(f6, f7)));
#pragma unroll
            for (int o = 1; o < 16; o <<= 1)
                tmax = fmaxf(tmax, __shfl_xor_sync(0xffffffffu, tmax, o));
            float nm = fmaxf(mrun[i], tmax);
            float ssum = __expf(f0 - nm) + __expf(f1 - nm) + __expf(f2 - nm) + __expf(f3 - nm)
                       + __expf(f4 - nm) + __expf(f5 - nm) + __expf(f6 - nm) + __expf(f7 - nm);
#pragma unroll
            for (int o = 1; o < 16; o <<= 1)
                ssum += __shfl_xor_sync(0xffffffffu, ssum, o);
            lrun[i] = lrun[i] * __expf(mrun[i] - nm) + ssum;
            mrun[i] = nm;

            float* arow = attnB + (size_t)(q0 + tm + i) * SEQ + kt * 128;
            *(float4*)(arow + c0)      = make_float4(f0, f1, f2, f3);
            *(float4*)(arow + 64 + c0) = make_float4(f4, f5, f6, f7);
        }
    }

    if (tx == 0) {
#pragma unroll
        for (int i = 0; i < 8; i++) {
            g_m[bh * SEQ + q0 + tm + i] = mrun[i];
            g_l[bh * SEQ + q0 + tm + i] = lrun[i];
        }
    }
}

// =======================================================================
// Pass 2: read raw S, p = exp(s-m)/l, write p (attn_weights output),
// accumulate O = P @ V, write O to out.
// smem: Ps2 packed [n][m] ld129 (132KB) + Vs [n][d] (64KB).
// =======================================================================
__global__ __launch_bounds__(256, 1)
void attn_pass2(const float* __restrict__ v_s, float* __restrict__ attn,
                float* __restrict__ out) {
    extern __shared__ char smem[];
    ull   (*Ps2)[129] = reinterpret_cast<ull(*)[129]>(smem);
    float (*Vs)[128]  = reinterpret_cast<float(*)[128]>(smem + 132096);

    const int t  = threadIdx.x;
    const int bh = blockIdx.y;
    const int q0 = blockIdx.x * 128;
    const float* Vg = v_s + (size_t)bh * SEQ * HD;
    float* attnB = attn + (size_t)bh * SEQ * SEQ;

    const int ty = t >> 4, tx = t & 15;
    const int tm = ty * 8, c0 = tx * 4;

    float mr[8], li[8];
#pragma unroll
    for (int i = 0; i < 8; i++) {
        mr[i] = g_m[bh * SEQ + q0 + tm + i];
        li[i] = 1.0f / g_l[bh * SEQ + q0 + tm + i];
    }

    ull acco[8][4];
#pragma unroll
    for (int i = 0; i < 8; i++)
#pragma unroll
        for (int j = 0; j < 4; j++) acco[i][j] = 0ULL;

    const int vsub = t >> 5;   // 0..7
    const int vd4  = t & 31;   // float4 column within row

    for (int kt = 0; kt < 16; kt++) {
        __syncthreads();  // previous PV gemm done before overwriting Vs/Ps2
        // V tile: natural [n][d], fully coalesced.
#pragma unroll 4
        for (int it = 0; it < 16; it++) {
            int row = it * 8 + vsub;
            *(float4*)&Vs[row][vd4 * 4] =
                *(const float4*)(Vg + (size_t)(kt * 128 + row) * HD + vd4 * 4);
        }
        // p: read raw s, exponentiate+normalize, write back, stage transposed.
#pragma unroll
        for (int i = 0; i < 8; i++) {
            float* arow = attnB + (size_t)(q0 + tm + i) * SEQ + kt * 128;
            float4 s0 = *(const float4*)(arow + c0);
            float4 s1 = *(const float4*)(arow + 64 + c0);
            float p0 = __expf(s0.x - mr[i]) * li[i];
            float p1 = __expf(s0.y - mr[i]) * li[i];
            float p2 = __expf(s0.z - mr[i]) * li[i];
            float p3 = __expf(s0.w - mr[i]) * li[i];
            float p4 = __expf(s1.x - mr[i]) * li[i];
            float p5 = __expf(s1.y - mr[i]) * li[i];
            float p6 = __expf(s1.z - mr[i]) * li[i];
            float p7 = __expf(s1.w - mr[i]) * li[i];
            *(float4*)(arow + c0)      = make_float4(p0, p1, p2, p3);
            *(float4*)(arow + 64 + c0) = make_float4(p4, p5, p6, p7);
            Ps2[c0 + 0][tm + i] = packdup(p0);
            Ps2[c0 + 1][tm + i] = packdup(p1);
            Ps2[c0 + 2][tm + i] = packdup(p2);
            Ps2[c0 + 3][tm + i] = packdup(p3);
            Ps2[64 + c0 + 0][tm + i] = packdup(p4);
            Ps2[64 + c0 + 1][tm + i] = packdup(p5);
            Ps2[64 + c0 + 2][tm + i] = packdup(p6);
            Ps2[64 + c0 + 3][tm + i] = packdup(p7);
        }
        __syncthreads();

#pragma unroll 8
        for (int kk = 0; kk < 128; kk++) {
            ull a2[8];
#pragma unroll
            for (int i = 0; i < 8; i++) a2[i] = Ps2[kk][tm + i];
            ulonglong2 bA = *(const ulonglong2*)&Vs[kk][c0];
            ulonglong2 bB = *(const ulonglong2*)&Vs[kk][64 + c0];
#pragma unroll
            for (int i = 0; i < 8; i++) {
                fma2(acco[i][0], a2[i], bA.x);
                fma2(acco[i][1], a2[i], bA.y);
                fma2(acco[i][2], a2[i], bB.x);
                fma2(acco[i][3], a2[i], bB.y);
            }
        }
    }

    const int b = bh >> 5, h = bh & 31;
#pragma unroll
    for (int i = 0; i < 8; i++) {
        float* orow = out + (size_t)(b * SEQ + q0 + tm + i) * HID + h * HD;
        float4 o0 = make_float4(lo32(acco[i][0]), hi32(acco[i][0]),
                                lo32(acco[i][1]), hi32(acco[i][1]));
        float4 o1 = make_float4(lo32(acco[i][2]), hi32(acco[i][2]),
                                lo32(acco[i][3]), hi32(acco[i][3]));
        *(float4*)(orow + c0)      = o0;
        *(float4*)(orow + 64 + c0) = o1;
    }
}

// =======================================================================
// Launch: 3x QKV GEMM -> pass1 (scores+stats) -> pass2 (softmax+PV).
// Output layout: [ out (2*2048*4096) | attn_weights (2*32*2048*2048) ].
// =======================================================================
extern "C" void kernel_launch(void* const* d_in, const int* in_sizes, int n_in,
                              void* d_out, int out_size) {
    (void)in_sizes; (void)n_in; (void)out_size;
    const float* X  = (const float*)d_in[0];
    const float* wq = (const float*)d_in[1];
    const float* wk = (const float*)d_in[2];
    const float* wv = (const float*)d_in[3];
    float* out  = (float*)d_out;
    float* attn = out + (size_t)MTOK * HID;  // 16,777,216 floats of `out` first

    void* sym = nullptr;
    cudaGetSymbolAddress(&sym, g_qkv);
    float* qs = (float*)sym;
    float* ks = qs + (size_t)MTOK * HID;
    float* vs = ks + (size_t)MTOK * HID;

    cudaFuncSetAttribute(attn_pass1, cudaFuncAttributeMaxDynamicSharedMemorySize, 196608);
    cudaFuncSetAttribute(attn_pass2, cudaFuncAttributeMaxDynamicSharedMemorySize, 197632);

    dim3 gg(HID / 128, MTOK / 128);  // 32 x 32
    gemm_qkv<<<gg, 256>>>(X, wq, qs);
    gemm_qkv<<<gg, 256>>>(X, wk, ks);
    gemm_qkv<<<gg, 256>>>(X, wv, vs);

    dim3 ga(SEQ / 128, BH);          // 16 x 64
    attn_pass1<<<ga, 256, 196608>>>(qs, ks, attn);
    attn_pass2<<<ga, 256, 197632>>>(vs, attn, out);
}

// round 3
// speedup vs baseline: 2.2108x; 2.2108x over previous
#include <cuda_runtime.h>
#include <cuda_bf16.h>
#include <cstdint>

#define HID   4096
#define NH    32
#define HD    128
#define BATCH 2
#define SEQ   2048
#define MTOK  (BATCH*SEQ)   /* 4096 tokens */
#define BH    (BATCH*NH)    /* 64 (batch, head) pairs */
#define MAT   (HID*HID)     /* 16,777,216 elements per matrix */

typedef unsigned long long ull;

// fp32 scratch: Q|K|V each [bh][s][d] (64 MB each) + softmax stats.
__device__ float g_qkv[3ULL * MTOK * HID];
__device__ float g_m[BH * SEQ];
__device__ float g_l[BH * SEQ];
// bf16 split scratch: x0,x1,wq0,wq1,wk0,wk1,wv0,wv1 (8 x 32 MB).
__device__ __nv_bfloat16 g_bs[8ULL * MAT];

// ---------------- packed f32x2 helpers (attention passes) ----------------
__device__ __forceinline__ void fma2(ull &d, ull a, ull b) {
    asm("fma.rn.f32x2 %0, %1, %2, %0;" : "+l"(d) : "l"(a), "l"(b));
}
__device__ __forceinline__ ull packdup(float x) {
    unsigned u = __float_as_uint(x);
    return ((ull)u << 32) | (ull)u;
}
__device__ __forceinline__ float lo32(ull v) { return __uint_as_float((unsigned)v); }
__device__ __forceinline__ float hi32(ull v) { return __uint_as_float((unsigned)(v >> 32)); }

// ---------------- async-copy / mma helpers (sm_80-level PTX only) ----------------
__device__ __forceinline__ uint32_t s2u(const void* p) {
    uint32_t a;
    asm("{ .reg .u64 t; cvta.to.shared.u64 t, %1; cvt.u32.u64 %0, t; }"
        : "=r"(a) : "l"(p));
    return a;
}
__device__ __forceinline__ void cp16(uint32_t dst, const void* src) {
    asm volatile("cp.async.cg.shared.global [%0], [%1], 16;" :: "r"(dst), "l"(src));
}
__device__ __forceinline__ void cp_commit() {
    asm volatile("cp.async.commit_group;" ::: "memory");
}
__device__ __forceinline__ void cp_wait1() {
    asm volatile("cp.async.wait_group 1;" ::: "memory");
}
__device__ __forceinline__ void ldsm4(uint32_t* r, uint32_t addr) {
    asm volatile("ldmatrix.sync.aligned.m8n8.x4.shared.b16 {%0,%1,%2,%3}, [%4];"
                 : "=r"(r[0]), "=r"(r[1]), "=r"(r[2]), "=r"(r[3]) : "r"(addr));
}
__device__ __forceinline__ void mma16816(float* d, const uint32_t* a,
                                         uint32_t b0, uint32_t b1) {
    asm volatile("mma.sync.aligned.m16n8k16.row.col.f32.bf16.bf16.f32 "
                 "{%0,%1,%2,%3}, {%4,%5,%6,%7}, {%8,%9}, {%0,%1,%2,%3};"
                 : "+f"(d[0]), "+f"(d[1]), "+f"(d[2]), "+f"(d[3])
                 : "r"(a[0]), "r"(a[1]), "r"(a[2]), "r"(a[3]), "r"(b0), "r"(b1));
}

// =======================================================================
// Kernel 0: fp32 -> (bf16 hi, bf16 lo) split, 4 elems/thread.
// =======================================================================
__global__ __launch_bounds__(256)
void split_bf16(const float* __restrict__ src, __nv_bfloat16* __restrict__ d0,
                __nv_bfloat16* __restrict__ d1) {
    int i = blockIdx.x * 256 + threadIdx.x;   // float4 index
    float4 v = ((const float4*)src)[i];
    __nv_bfloat16 h0 = __float2bfloat16(v.x);
    __nv_bfloat16 h1 = __float2bfloat16(v.y);
    __nv_bfloat16 h2 = __float2bfloat16(v.z);
    __nv_bfloat16 h3 = __float2bfloat16(v.w);
    __nv_bfloat16 l0 = __float2bfloat16(v.x - __bfloat162float(h0));
    __nv_bfloat16 l1 = __float2bfloat16(v.y - __bfloat162float(h1));
    __nv_bfloat16 l2 = __float2bfloat16(v.z - __bfloat162float(h2));
    __nv_bfloat16 l3 = __float2bfloat16(v.w - __bfloat162float(h3));
    ull ph = (ull)__bfloat16_as_ushort(h0) | ((ull)__bfloat16_as_ushort(h1) << 16)
           | ((ull)__bfloat16_as_ushort(h2) << 32) | ((ull)__bfloat16_as_ushort(h3) << 48);
    ull pl = (ull)__bfloat16_as_ushort(l0) | ((ull)__bfloat16_as_ushort(l1) << 16)
           | ((ull)__bfloat16_as_ushort(l2) << 32) | ((ull)__bfloat16_as_ushort(l3) << 48);
    ((ull*)d0)[i] = ph;
    ((ull*)d1)[i] = pl;
}

// =======================================================================
// Kernel 1: split-bf16 GEMM on mma.sync (HMMA tensor path).
// Y[m,n] = sum_k X[m,k] * W[n,k]; W row-major [n,k] == col-major B. 
// CTA tile 128x128 (n-tile == 1 head), warp tile 64x32, K-chunk 64,
// 2-stage cp.async pipeline, xor-swizzled smem for ldmatrix.
// blockIdx.z in {0,1,2} selects wq/wk/wv; dst layout [bh][s][d].
// =======================================================================
#define KCH   64
#define NCHUNK (HID / KCH)      /* 64 */
#define STG   65536             /* bytes per pipeline stage */
#define A0_OFF 0
#define A1_OFF 16384
#define B0_OFF 32768
#define B1_OFF 49152

__global__ __launch_bounds__(256, 1)
void gemm_qkv_mma(const __nv_bfloat16* __restrict__ x0,
                  const __nv_bfloat16* __restrict__ x1,
                  const __nv_bfloat16* __restrict__ w_all,  /* wq0|wq1|wk0|wk1|wv0|wv1 */
                  float* __restrict__ dst_base) {
    extern __shared__ char smem[];
    const int t = threadIdx.x, lane = t & 31, wid = t >> 5;
    const int wm = wid >> 2, wn = wid & 3;             // warp grid 2(m) x 4(n)
    const int bn = blockIdx.x * 128;
    const int bm = blockIdx.y * 128;
    const int z  = blockIdx.z;

    const __nv_bfloat16* w0 = w_all + (size_t)(2 * z) * MAT;
    const __nv_bfloat16* w1 = w0 + MAT;
    float* dst = dst_base + (size_t)z * MTOK * HID;
    const uint32_t sb = s2u(smem);

    float acc[4][4][4];
#pragma unroll
    for (int i = 0; i < 4; i++)
#pragma unroll
        for (int j = 0; j < 4; j++)
#pragma unroll
            for (int r = 0; r < 4; r++) acc[i][j][r] = 0.0f;

    // -------- stage loader: 16 x cp.async(16B) per thread --------
    auto load_stage = [&](int st, int k0) {
        const uint32_t base = sb + (uint32_t)st * STG;
#pragma unroll
        for (int i = 0; i < 4; i++) {
            int u = t + 256 * i;
            int row = u >> 3, ch = u & 7;
            uint32_t off = (uint32_t)row * 128 + (uint32_t)((ch ^ (row & 7)) * 16);
            size_t ga = (size_t)(bm + row) * HID + k0 + ch * 8;
            size_t gb = (size_t)(bn + row) * HID + k0 + ch * 8;
            cp16(base + A0_OFF + off, x0 + ga);
            cp16(base + A1_OFF + off, x1 + ga);
            cp16(base + B0_OFF + off, w0 + gb);
            cp16(base + B1_OFF + off, w1 + gb);
        }
    };

    load_stage(0, 0);
    cp_commit();

    const int tq = lane >> 3, r8 = lane & 7;

    for (int c = 0; c < NCHUNK; c++) {
        if (c + 1 < NCHUNK) load_stage((c + 1) & 1, (c + 1) * KCH);
        cp_commit();
        cp_wait1();            // stage c resident
        __syncthreads();

        const uint32_t base = sb + (uint32_t)(c & 1) * STG;
#pragma unroll
        for (int s = 0; s < 4; s++) {     // four k16 steps in the 64-chunk
            uint32_t a0f[4][4], a1f[4][4], b0f[2][4], b1f[2][4];
#pragma unroll
            for (int i = 0; i < 4; i++) {
                int row = wm * 64 + i * 16 + (tq & 1) * 8 + r8;
                int ch  = s * 2 + (tq >> 1);
                uint32_t off = (uint32_t)row * 128 + (uint32_t)((ch ^ (row & 7)) * 16);
                ldsm4(a0f[i], base + A0_OFF + off);
                ldsm4(a1f[i], base + A1_OFF + off);
            }
#pragma unroll
            for (int j = 0; j < 2; j++) {
                int row = wn * 32 + j * 16 + (tq >> 1) * 8 + r8;
                int ch  = s * 2 + (tq & 1);
                uint32_t off = (uint32_t)row * 128 + (uint32_t)((ch ^ (row & 7)) * 16);
                ldsm4(b0f[j], base + B0_OFF + off);
                ldsm4(b1f[j], base + B1_OFF + off);
            }
#pragma unroll
            for (int i = 0; i < 4; i++) {
#pragma unroll
                for (int jj = 0; jj < 4; jj++) {
                    const int jh = jj >> 1, jp = (jj & 1) * 2;
                    mma16816(acc[i][jj], a0f[i], b0f[jh][jp], b0f[jh][jp + 1]); // hi*hi
                    mma16816(acc[i][jj], a0f[i], b1f[jh][jp], b1f[jh][jp + 1]); // hi*lo
                    mma16816(acc[i][jj], a1f[i], b0f[jh][jp], b0f[jh][jp + 1]); // lo*hi
                }
            }
        }
        __syncthreads();       // compute done before next iter overwrites this stage
    }

    // -------- epilogue: scatter to [bh][s][d]; n-tile is exactly one head --------
    const int h = bn >> 7;                 // 128-wide aligned n-tile == head index
    const int lr = lane >> 2, lc = (lane & 3) * 2;
#pragma unroll
    for (int i = 0; i < 4; i++) {
#pragma unroll
        for (int jj = 0; jj < 4; jj++) {
            int m0 = bm + wm * 64 + i * 16 + lr;
            int d  = wn * 32 + jj * 8 + lc;
            int b0_ = m0 >> 11, s0 = m0 & 2047;
            int m1 = m0 + 8;
            int b1_ = m1 >> 11, s1 = m1 & 2047;
            float* p0 = dst + ((size_t)(b0_ * NH + h) * SEQ + s0) * HD + d;
            float* p1 = dst + ((size_t)(b1_ * NH + h) * SEQ + s1) * HD + d;
            *(float2*)p0 = make_float2(acc[i][jj][0], acc[i][jj][1]);
            *(float2*)p1 = make_float2(acc[i][jj][2], acc[i][jj][3]);
        }
    }
}

// =======================================================================
// Pass 1: per (bh, q-tile of 128): compute scaled S = (Q/sqrt(d)) K^T,
// write raw S to attn buffer, keep online row max / sum(exp).
// =======================================================================
__global__ __launch_bounds__(256, 1)
void attn_pass1(const float* __restrict__ q_s, const float* __restrict__ k_s,
                float* __restrict__ attn) {
    extern __shared__ char smem[];
    ull   (*Qs2)[128] = reinterpret_cast<ull(*)[128]>(smem);
    float (*Ks)[128]  = reinterpret_cast<float(*)[128]>(smem + 131072);

    const int t  = threadIdx.x;
    const int bh = blockIdx.y;
    const int q0 = blockIdx.x * 128;
    const float scale = 0.08838834764831845f;  // 1/sqrt(128)

    const float* Qg = q_s + ((size_t)bh * SEQ + q0) * HD;
    const float* Kg = k_s + (size_t)bh * SEQ * HD;
    float* attnB = attn + (size_t)bh * SEQ * SEQ;

    const int lrow = t & 127, lhalf = t >> 7;
    {
        const float4* src = (const float4*)(Qg + (size_t)lrow * HD);
#pragma unroll 4
        for (int i = 0; i < 16; i++) {
            int d4 = i * 2 + lhalf;
            float4 v = src[d4];
            Qs2[4 * d4 + 0][lrow] = packdup(v.x * scale);
            Qs2[4 * d4 + 1][lrow] = packdup(v.y * scale);
            Qs2[4 * d4 + 2][lrow] = packdup(v.z * scale);
            Qs2[4 * d4 + 3][lrow] = packdup(v.w * scale);
        }
    }
    const int ty = t >> 4, tx = t & 15;
    const int tm = ty * 8, c0 = tx * 4;

    float mrun[8], lrun[8];
#pragma unroll
    for (int i = 0; i < 8; i++) { mrun[i] = -1e30f; lrun[i] = 0.0f; }

    for (int kt = 0; kt < 16; kt++) {
        __syncthreads();
        {
            const float4* ksrc = (const float4*)(Kg + (size_t)(kt * 128 + lrow) * HD);
#pragma unroll 4
            for (int i = 0; i < 16; i++) {
                int d4 = i * 2 + lhalf;
                float4 v = ksrc[d4];
                Ks[4 * d4 + 0][lrow] = v.x;
                Ks[4 * d4 + 1][lrow] = v.y;
                Ks[4 * d4 + 2][lrow] = v.z;
                Ks[4 * d4 + 3][lrow] = v.w;
            }
        }
        __syncthreads();

        ull acc[8][4];
#pragma unroll
        for (int i = 0; i < 8; i++)
#pragma unroll
            for (int j = 0; j < 4; j++) acc[i][j] = 0ULL;

#pragma unroll 8
        for (int kk = 0; kk < 128; kk++) {
            ull a2[8];
#pragma unroll
            for (int i = 0; i < 8; i++) a2[i] = Qs2[kk][tm + i];
            ulonglong2 bA = *(const ulonglong2*)&Ks[kk][c0];
            ulonglong2 bB = *(const ulonglong2*)&Ks[kk][64 + c0];
#pragma unroll
            for (int i = 0; i < 8; i++) {
                fma2(acc[i][0], a2[i], bA.x);
                fma2(acc[i][1], a2[i], bA.y);
                fma2(acc[i][2], a2[i], bB.x);
                fma2(acc[i][3], a2[i], bB.y);
            }
        }

#pragma unroll
        for (int i = 0; i < 8; i++) {
            float f0 = lo32(acc[i][0]), f1 = hi32(acc[i][0]);
            float f2 = lo32(acc[i][1]), f3 = hi32(acc[i][1]);
            float f4 = lo32(acc[i][2]), f5 = hi32(acc[i][2]);
            float f6 = lo32(acc[i][3]), f7 = hi32(acc[i][3]);
            float tmax = fmaxf(fmaxf(fmaxf(f0, f1), fmaxf(f2, f3)),
                               fmaxf(fmaxf(f4, f5), fmaxf(f6, f7)));
#pragma unroll
            for (int o = 1; o < 16; o <<= 1)
                tmax = fmaxf(tmax, __shfl_xor_sync(0xffffffffu, tmax, o));
            float nm = fmaxf(mrun[i], tmax);
            float ssum = __expf(f0 - nm) + __expf(f1 - nm) + __expf(f2 - nm) + __expf(f3 - nm)
                       + __expf(f4 - nm) + __expf(f5 - nm) + __expf(f6 - nm) + __expf(f7 - nm);
#pragma unroll
            for (int o = 1; o < 16; o <<= 1)
                ssum += __shfl_xor_sync(0xffffffffu, ssum, o);
            lrun[i] = lrun[i] * __expf(mrun[i] - nm) + ssum;
            mrun[i] = nm;

            float* arow = attnB + (size_t)(q0 + tm + i) * SEQ + kt * 128;
            *(float4*)(arow + c0)      = make_float4(f0, f1, f2, f3);
            *(float4*)(arow + 64 + c0) = make_float4(f4, f5, f6, f7);
        }
    }

    if (tx == 0) {
#pragma unroll
        for (int i = 0; i < 8; i++) {
            g_m[bh * SEQ + q0 + tm + i] = mrun[i];
            g_l[bh * SEQ + q0 + tm + i] = lrun[i];
        }
    }
}

// =======================================================================
// Pass 2: read raw S, p = exp(s-m)/l, write p, accumulate O = P @ V.
// =======================================================================
__global__ __launch_bounds__(256, 1)
void attn_pass2(const float* __restrict__ v_s, float* __restrict__ attn,
                float* __restrict__ out) {
    extern __shared__ char smem[];
    ull   (*Ps2)[129] = reinterpret_cast<ull(*)[129]>(smem);
    float (*Vs)[128]  = reinterpret_cast<float(*)[128]>(smem + 132096);

    const int t  = threadIdx.x;
    const int bh = blockIdx.y;
    const int q0 = blockIdx.x * 128;
    const float* Vg = v_s + (size_t)bh * SEQ * HD;
    float* attnB = attn + (size_t)bh * SEQ * SEQ;

    const int ty = t >> 4, tx = t & 15;
    const int tm = ty * 8, c0 = tx * 4;

    float mr[8], li[8];
#pragma unroll
    for (int i = 0; i < 8; i++) {
        mr[i] = g_m[bh * SEQ + q0 + tm + i];
        li[i] = 1.0f / g_l[bh * SEQ + q0 + tm + i];
    }

    ull acco[8][4];
#pragma unroll
    for (int i = 0; i < 8; i++)
#pragma unroll
        for (int j = 0; j < 4; j++) acco[i][j] = 0ULL;

    const int vsub = t >> 5;
    const int vd4  = t & 31;

    for (int kt = 0; kt < 16; kt++) {
        __syncthreads();
#pragma unroll 4
        for (int it = 0; it < 16; it++) {
            int row = it * 8 + vsub;
            *(float4*)&Vs[row][vd4 * 4] =
                *(const float4*)(Vg + (size_t)(kt * 128 + row) * HD + vd4 * 4);
        }
#pragma unroll
        for (int i = 0; i < 8; i++) {
            float* arow = attnB + (size_t)(q0 + tm + i) * SEQ + kt * 128;
            float4 s0 = *(const float4*)(arow + c0);
            float4 s1 = *(const float4*)(arow + 64 + c0);
            float p0 = __expf(s0.x - mr[i]) * li[i];
            float p1 = __expf(s0.y - mr[i]) * li[i];
            float p2 = __expf(s0.z - mr[i]) * li[i];
            float p3 = __expf(s0.w - mr[i]) * li[i];
            float p4 = __expf(s1.x - mr[i]) * li[i];
            float p5 = __expf(s1.y - mr[i]) * li[i];
            float p6 = __expf(s1.z - mr[i]) * li[i];
            float p7 = __expf(s1.w - mr[i]) * li[i];
            *(float4*)(arow + c0)      = make_float4(p0, p1, p2, p3);
            *(float4*)(arow + 64 + c0) = make_float4(p4, p5, p6, p7);
            Ps2[c0 + 0][tm + i] = packdup(p0);
            Ps2[c0 + 1][tm + i] = packdup(p1);
            Ps2[c0 + 2][tm + i] = packdup(p2);
            Ps2[c0 + 3][tm + i] = packdup(p3);
            Ps2[64 + c0 + 0][tm + i] = packdup(p4);
            Ps2[64 + c0 + 1][tm + i] = packdup(p5);
            Ps2[64 + c0 + 2][tm + i] = packdup(p6);
            Ps2[64 + c0 + 3][tm + i] = packdup(p7);
        }
        __syncthreads();

#pragma unroll 8
        for (int kk = 0; kk < 128; kk++) {
            ull a2[8];
#pragma unroll
            for (int i = 0; i < 8; i++) a2[i] = Ps2[kk][tm + i];
            ulonglong2 bA = *(const ulonglong2*)&Vs[kk][c0];
            ulonglong2 bB = *(const ulonglong2*)&Vs[kk][64 + c0];
#pragma unroll
            for (int i = 0; i < 8; i++) {
                fma2(acco[i][0], a2[i], bA.x);
                fma2(acco[i][1], a2[i], bA.y);
                fma2(acco[i][2], a2[i], bB.x);
                fma2(acco[i][3], a2[i], bB.y);
            }
        }
    }

    const int b = bh >> 5, h = bh & 31;
#pragma unroll
    for (int i = 0; i < 8; i++) {
        float* orow = out + (size_t)(b * SEQ + q0 + tm + i) * HID + h * HD;
        float4 o0 = make_float4(lo32(acco[i][0]), hi32(acco[i][0]),
                                lo32(acco[i][1]), hi32(acco[i][1]));
        float4 o1 = make_float4(lo32(acco[i][2]), hi32(acco[i][2]),
                                lo32(acco[i][3]), hi32(acco[i][3]));
        *(float4*)(orow + c0)      = o0;
        *(float4*)(orow + 64 + c0) = o1;
    }
}

// =======================================================================
// Launch: split -> mma.sync QKV GEMM -> pass1 -> pass2.
// Output layout: [ out (2*2048*4096) | attn_weights (2*32*2048*2048) ].
// =======================================================================
extern "C" void kernel_launch(void* const* d_in, const int* in_sizes, int n_in,
                              void* d_out, int out_size) {
    (void)in_sizes; (void)n_in; (void)out_size;
    const float* X  = (const float*)d_in[0];
    const float* wq = (const float*)d_in[1];
    const float* wk = (const float*)d_in[2];
    const float* wv = (const float*)d_in[3];
    float* out  = (float*)d_out;
    float* attn = out + (size_t)MTOK * HID;

    void* sym = nullptr;
    cudaGetSymbolAddress(&sym, g_qkv);
    float* qs = (float*)sym;
    void* bsym = nullptr;
    cudaGetSymbolAddress(&bsym, g_bs);
    __nv_bfloat16* bs = (__nv_bfloat16*)bsym;

    cudaFuncSetAttribute(gemm_qkv_mma, cudaFuncAttributeMaxDynamicSharedMemorySize, 2 * STG);
    cudaFuncSetAttribute(attn_pass1, cudaFuncAttributeMaxDynamicSharedMemorySize, 196608);
    cudaFuncSetAttribute(attn_pass2, cudaFuncAttributeMaxDynamicSharedMemorySize, 197632);

    // fp32 -> bf16 hi/lo splits  (x0,x1 | wq0,wq1 | wk0,wk1 | wv0,wv1)
    const int n4 = MAT / 4;
    split_bf16<<<n4 / 256, 256>>>(X,  bs + 0ULL * MAT, bs + 1ULL * MAT);
    split_bf16<<<n4 / 256, 256>>>(wq, bs + 2ULL * MAT, bs + 3ULL * MAT);
    split_bf16<<<n4 / 256, 256>>>(wk, bs + 4ULL * MAT, bs + 5ULL * MAT);
    split_bf16<<<n4 / 256, 256>>>(wv, bs + 6ULL * MAT, bs + 7ULL * MAT);

    // QKV on tensor cores (legacy mma.sync): grid (n=32, m=32, 3 matrices)
    dim3 gg(HID / 128, MTOK / 128, 3);
    gemm_qkv_mma<<<gg, 256, 2 * STG>>>(bs + 0ULL * MAT, bs + 1ULL * MAT,
                                       bs + 2ULL * MAT, qs);

    dim3 ga(SEQ / 128, BH);
    attn_pass1<<<ga, 256, 196608>>>(qs, qs + (size_t)MTOK * HID, attn);
    attn_pass2<<<ga, 256, 197632>>>(qs + 2ULL * MTOK * HID, attn, out);
}